// round 2
// baseline (speedup 1.0000x reference)
#include <cuda_runtime.h>
#include <math.h>

#define NMAX 100000
#define EMAX 1600000
#define D_IN 512
#define D_H  128
#define D_OUT 40
#define SCAN_B 512

// ---------------- scratch (static device globals; no dynamic alloc) -------------
__device__ int   g_cnt[NMAX];
__device__ int   g_local[NMAX];
__device__ int   g_partials[512];
__device__ int   g_row_ptr[NMAX + 1];
__device__ int   g_cursor[NMAX];
__device__ int   g_col[EMAX];
__device__ float g_dinv[NMAX];
__device__ float g_h1 [NMAX * D_H];
__device__ float g_h1a[NMAX * D_H];
__device__ float g_h2 [NMAX * D_OUT];

// ---------------- degree / CSR build -------------------------------------------
__global__ void zero_cnt_kernel(int n) {
    int i = blockIdx.x * blockDim.x + threadIdx.x;
    if (i < n) g_cnt[i] = 0;
}

__global__ void count_kernel(const int* __restrict__ dst, int e_cnt) {
    int e = blockIdx.x * blockDim.x + threadIdx.x;
    if (e < e_cnt) atomicAdd(&g_cnt[dst[e]], 1);
}

// block-level exclusive scan of g_cnt -> g_local, block sums -> g_partials
__global__ void scan_block_kernel(int n) {
    __shared__ int sh[SCAN_B];
    int i = blockIdx.x * SCAN_B + threadIdx.x;
    int v = (i < n) ? g_cnt[i] : 0;
    sh[threadIdx.x] = v;
    __syncthreads();
    #pragma unroll
    for (int off = 1; off < SCAN_B; off <<= 1) {
        int t = 0;
        if ((int)threadIdx.x >= off) t = sh[threadIdx.x - off];
        __syncthreads();
        sh[threadIdx.x] += t;
        __syncthreads();
    }
    if (i < n) g_local[i] = sh[threadIdx.x] - v;  // exclusive
    if (threadIdx.x == SCAN_B - 1) g_partials[blockIdx.x] = sh[SCAN_B - 1];
}

__global__ void scan_partials_kernel(int nb) {
    if (threadIdx.x == 0 && blockIdx.x == 0) {
        int s = 0;
        for (int i = 0; i < nb; i++) {
            int v = g_partials[i];
            g_partials[i] = s;
            s += v;
        }
    }
}

// finalize row_ptr, cursor, dinv
__global__ void scan_add_kernel(int n, int e_cnt) {
    int i = blockIdx.x * SCAN_B + threadIdx.x;
    if (i < n) {
        int r = g_local[i] + g_partials[blockIdx.x];
        g_row_ptr[i] = r;
        g_cursor[i]  = r;
        // degree includes the self-loop (+1); always >= 1
        g_dinv[i] = rsqrtf((float)(g_cnt[i] + 1));
    }
    if (i == 0) g_row_ptr[n] = e_cnt;
}

__global__ void fill_csr_kernel(const int* __restrict__ src,
                                const int* __restrict__ dst, int e_cnt) {
    int e = blockIdx.x * blockDim.x + threadIdx.x;
    if (e < e_cnt) {
        int d = dst[e];
        int pos = atomicAdd(&g_cursor[d], 1);
        g_col[pos] = src[e];
    }
}

// ---------------- GEMM1: h1 = x @ W1   (M x 512) @ (512 x 128) ------------------
// BM=64, BN=128, BK=32, 256 threads, each thread 8x4 outputs
__global__ __launch_bounds__(256) void gemm1_kernel(const float* __restrict__ A,
                                                    const float* __restrict__ B, int M) {
    __shared__ float As[64][32];
    __shared__ float Bs[32][128];
    const int tid = threadIdx.x;
    const int tn = tid & 31;   // 0..31 -> col group of 4
    const int tm = tid >> 5;   // 0..7  -> row group of 8
    const int row0 = blockIdx.x * 64;

    float acc[8][4];
    #pragma unroll
    for (int i = 0; i < 8; i++)
        #pragma unroll
        for (int j = 0; j < 4; j++) acc[i][j] = 0.f;

    for (int k0 = 0; k0 < D_IN; k0 += 32) {
        #pragma unroll
        for (int i = 0; i < 8; i++) {
            int idx = tid + i * 256;
            int m = idx >> 5, k = idx & 31;
            int r = row0 + m;
            As[m][k] = (r < M) ? A[r * D_IN + k0 + k] : 0.f;
        }
        #pragma unroll
        for (int i = 0; i < 16; i++) {
            int idx = tid + i * 256;
            int k = idx >> 7, nn = idx & 127;
            Bs[k][nn] = B[(k0 + k) * D_H + nn];
        }
        __syncthreads();
        #pragma unroll
        for (int k = 0; k < 32; k++) {
            float4 bv = *(const float4*)&Bs[k][tn * 4];
            #pragma unroll
            for (int i = 0; i < 8; i++) {
                float a = As[tm * 8 + i][k];
                acc[i][0] = fmaf(a, bv.x, acc[i][0]);
                acc[i][1] = fmaf(a, bv.y, acc[i][1]);
                acc[i][2] = fmaf(a, bv.z, acc[i][2]);
                acc[i][3] = fmaf(a, bv.w, acc[i][3]);
            }
        }
        __syncthreads();
    }
    #pragma unroll
    for (int i = 0; i < 8; i++) {
        int r = row0 + tm * 8 + i;
        if (r < M) {
            float4 o = make_float4(acc[i][0], acc[i][1], acc[i][2], acc[i][3]);
            *(float4*)&g_h1[r * D_H + tn * 4] = o;
        }
    }
}

// ---------------- Aggregation layer 1: warp per node, 128 cols -----------------
__global__ void agg1_kernel(const float* __restrict__ b1, int n) {
    int warp = (blockIdx.x * blockDim.x + threadIdx.x) >> 5;
    int lane = threadIdx.x & 31;
    if (warp >= n) return;
    const int node = warp;
    const int start = g_row_ptr[node];
    const int end   = g_row_ptr[node + 1];

    float4 acc = make_float4(0.f, 0.f, 0.f, 0.f);
    for (int e = start; e < end; e++) {
        int s = g_col[e];
        float ns = g_dinv[s];
        float4 v = *(const float4*)&g_h1[s * D_H + (lane << 2)];
        acc.x = fmaf(ns, v.x, acc.x);
        acc.y = fmaf(ns, v.y, acc.y);
        acc.z = fmaf(ns, v.z, acc.z);
        acc.w = fmaf(ns, v.w, acc.w);
    }
    float di = g_dinv[node];
    float4 sv = *(const float4*)&g_h1[node * D_H + (lane << 2)];
    float4 bb = *(const float4*)&b1[lane << 2];
    // out = di * (acc + di*self) + b, then ReLU
    float4 o;
    o.x = fmaxf(fmaf(di, fmaf(di, sv.x, acc.x), bb.x), 0.f);
    o.y = fmaxf(fmaf(di, fmaf(di, sv.y, acc.y), bb.y), 0.f);
    o.z = fmaxf(fmaf(di, fmaf(di, sv.z, acc.z), bb.z), 0.f);
    o.w = fmaxf(fmaf(di, fmaf(di, sv.w, acc.w), bb.w), 0.f);
    *(float4*)&g_h1a[node * D_H + (lane << 2)] = o;
}

// ---------------- GEMM2: h2 = h1a @ W2   (M x 128) @ (128 x 40) ----------------
// 32 nodes per block, 256 threads = 32 nodes x 8 groups of 5 cols.
// Shared: Ws 20KB + Hs 16.9KB = 37.4KB (< 48KB static limit)
__global__ __launch_bounds__(256) void gemm2_kernel(const float* __restrict__ W2, int M) {
    __shared__ float Ws[D_H * D_OUT];   // 20 KB
    __shared__ float Hs[D_H][33];       // k-major, padded
    const int tid = threadIdx.x;
    const int row0 = blockIdx.x * 32;

    for (int i = tid; i < D_H * D_OUT; i += 256) Ws[i] = W2[i];
    for (int i = tid; i < 32 * D_H; i += 256) {
        int nn = i >> 7, k = i & 127;
        float v = (row0 + nn < M) ? g_h1a[(row0 + nn) * D_H + k] : 0.f;
        Hs[k][nn] = v;
    }
    __syncthreads();

    const int nn = tid & 31;   // node in tile
    const int g  = tid >> 5;   // 0..7 -> 5-col group
    float acc[5];
    #pragma unroll
    for (int j = 0; j < 5; j++) acc[j] = 0.f;

    #pragma unroll 8
    for (int k = 0; k < D_H; k++) {
        float h = Hs[k][nn];
        const float* w = &Ws[k * D_OUT + g * 5];
        #pragma unroll
        for (int j = 0; j < 5; j++) acc[j] = fmaf(h, w[j], acc[j]);
    }
    if (row0 + nn < M) {
        float* op = &g_h2[(row0 + nn) * D_OUT + g * 5];
        #pragma unroll
        for (int j = 0; j < 5; j++) op[j] = acc[j];
    }
}

// ---------------- Aggregation layer 2 + bias + log_softmax ---------------------
__global__ void agg2_kernel(const float* __restrict__ b2, float* __restrict__ out, int n) {
    int warp = (blockIdx.x * blockDim.x + threadIdx.x) >> 5;
    int lane = threadIdx.x & 31;
    if (warp >= n) return;
    const int node = warp;
    const int start = g_row_ptr[node];
    const int end   = g_row_ptr[node + 1];
    const bool hi = (lane < 8);

    float acc0 = 0.f, acc1 = 0.f;
    for (int e = start; e < end; e++) {
        int s = g_col[e];
        float ns = g_dinv[s];
        const float* hp = &g_h2[s * D_OUT];
        acc0 = fmaf(ns, hp[lane], acc0);
        if (hi) acc1 = fmaf(ns, hp[lane + 32], acc1);
    }
    float di = g_dinv[node];
    const float* sp = &g_h2[node * D_OUT];
    float v0 = fmaf(di, fmaf(di, sp[lane], acc0), b2[lane]);
    float v1 = 0.f;
    if (hi) v1 = fmaf(di, fmaf(di, sp[lane + 32], acc1), b2[lane + 32]);

    // warp log_softmax over the 40 values
    float m = hi ? fmaxf(v0, v1) : v0;
    #pragma unroll
    for (int o = 16; o >= 1; o >>= 1)
        m = fmaxf(m, __shfl_xor_sync(0xffffffffu, m, o));
    float s = expf(v0 - m) + (hi ? expf(v1 - m) : 0.f);
    #pragma unroll
    for (int o = 16; o >= 1; o >>= 1)
        s += __shfl_xor_sync(0xffffffffu, s, o);
    float ls = logf(s);

    out[node * D_OUT + lane] = v0 - m - ls;
    if (hi) out[node * D_OUT + 32 + lane] = v1 - m - ls;
}

// ---------------- launch --------------------------------------------------------
extern "C" void kernel_launch(void* const* d_in, const int* in_sizes, int n_in,
                              void* d_out, int out_size) {
    const float* x   = (const float*)d_in[0];
    const int*   ei  = (const int*)d_in[1];    // edge_index is int32 (JAX x64 disabled)
    const float* W1  = (const float*)d_in[2];
    const float* b1  = (const float*)d_in[3];
    const float* W2  = (const float*)d_in[4];
    const float* b2  = (const float*)d_in[5];
    float* out = (float*)d_out;

    const int n = in_sizes[0] / D_IN;   // 100000
    const int e = in_sizes[1] / 2;      // 1600000
    const int* src = ei;
    const int* dst = ei + e;

    const int nb_scan = (n + SCAN_B - 1) / SCAN_B;

    zero_cnt_kernel<<<(n + 255) / 256, 256>>>(n);
    count_kernel<<<(e + 255) / 256, 256>>>(dst, e);
    scan_block_kernel<<<nb_scan, SCAN_B>>>(n);
    scan_partials_kernel<<<1, 32>>>(nb_scan);
    scan_add_kernel<<<nb_scan, SCAN_B>>>(n, e);
    fill_csr_kernel<<<(e + 255) / 256, 256>>>(src, dst, e);

    gemm1_kernel<<<(n + 63) / 64, 256>>>(x, W1, n);
    agg1_kernel<<<(n * 32 + 255) / 256, 256>>>(b1, n);
    gemm2_kernel<<<(n + 31) / 32, 256>>>(W2, n);
    agg2_kernel<<<(n * 32 + 255) / 256, 256>>>(b2, out, n);
}